// round 1
// baseline (speedup 1.0000x reference)
#include <cuda_runtime.h>
#include <cstdint>

#define TAGS       10
#define SEQ        512
#define BATCHN     8192
#define START_TAG  8
#define STOP_TAG   9
#define NEG_INF    (-10000.0f)

// Backpointer scratch: one u64 per (t, b), 10 tags x 4-bit nibbles.
// 512 * 8192 * 8 B = 33.5 MB static device scratch (allocation-free).
__device__ unsigned long long g_bp[(size_t)SEQ * BATCHN];

__device__ __forceinline__ void load_feat_row(float2 fr[5],
                                              const float* __restrict__ feats,
                                              int t, int b) {
    // feats[t][b][tag]: byte offset = (t*BATCHN + b)*10*4, multiple of 40 -> 8-aligned
    const float2* p = reinterpret_cast<const float2*>(
        feats + ((size_t)t * BATCHN + b) * TAGS);
#pragma unroll
    for (int i = 0; i < 5; i++) fr[i] = __ldg(p + i);
}

__global__ __launch_bounds__(64, 1)
void crf_viterbi_kernel(const float* __restrict__ feats,
                        const float* __restrict__ trans,
                        float* __restrict__ out) {
    const int b = blockIdx.x * blockDim.x + threadIdx.x;
    if (b >= BATCHN) return;

    // Transitions into registers (broadcast loads, fully unrolled indexing)
    float T[TAGS][TAGS];
#pragma unroll
    for (int n = 0; n < TAGS; n++)
#pragma unroll
        for (int p = 0; p < TAGS; p++)
            T[n][p] = __ldg(trans + n * TAGS + p);

    // init: NEG_INF except START_TAG = 0
    float fv[TAGS];
#pragma unroll
    for (int p = 0; p < TAGS; p++) fv[p] = NEG_INF;
    fv[START_TAG] = 0.0f;

    // software pipeline: prefetch feats row for t=0
    float2 fr[5];
    load_feat_row(fr, feats, 0, b);

    unsigned long long* __restrict__ bp_col = g_bp + b;

    for (int t = 0; t < SEQ; t++) {
        float f[TAGS];
#pragma unroll
        for (int i = 0; i < 5; i++) { f[2 * i] = fr[i].x; f[2 * i + 1] = fr[i].y; }
        // prefetch next row while computing this step
        if (t + 1 < SEQ) load_feat_row(fr, feats, t + 1, b);

        unsigned long long bits = 0ull;
        float nf[TAGS];
#pragma unroll
        for (int n = 0; n < TAGS; n++) {
            float best = fv[0] + T[n][0];
            int   bi   = 0;
#pragma unroll
            for (int p = 1; p < TAGS; p++) {
                float v = fv[p] + T[n][p];
                if (v > best) { best = v; bi = p; }   // strict > => first-index argmax
            }
            nf[n] = best + f[n];
            bits |= (unsigned long long)(unsigned)bi << (4 * n);
        }
#pragma unroll
        for (int n = 0; n < TAGS; n++) fv[n] = nf[n];

        bp_col[(size_t)t * BATCHN] = bits;   // coalesced STG.64 across the warp
    }

    // terminal = fv + trans[STOP_TAG]
    float best = fv[0] + T[STOP_TAG][0];
    int   tag  = 0;
#pragma unroll
    for (int p = 1; p < TAGS; p++) {
        float v = fv[p] + T[STOP_TAG][p];
        if (v > best) { best = v; tag = p; }
    }

    // outputs: [0:BATCHN) = path_score (f32), then best_path [SEQ][BATCHN] as f32
    out[b] = best;
    float* __restrict__ path = out + BATCHN;

    // backtrace: bp loads are address-independent of tag (prefetchable by unroll);
    // only the nibble extraction is the serial chain (cheap ALU).
#pragma unroll 8
    for (int t = SEQ - 1; t >= 0; t--) {
        path[(size_t)t * BATCHN + b] = (float)tag;
        unsigned long long w = bp_col[(size_t)t * BATCHN];
        tag = (int)((w >> (tag * 4)) & 0xFull);
    }
}

extern "C" void kernel_launch(void* const* d_in, const int* in_sizes, int n_in,
                              void* d_out, int out_size) {
    const float* feats = (const float*)d_in[0];
    const float* trans = (const float*)d_in[1];
    float* out = (float*)d_out;

    dim3 block(64);
    dim3 grid((BATCHN + 63) / 64);   // 128 blocks -> single wave, 2 warps/SM
    crf_viterbi_kernel<<<grid, block>>>(feats, trans, out);
}

// round 2
// speedup vs baseline: 1.0303x; 1.0303x over previous
#include <cuda_runtime.h>
#include <cstdint>

#define TAGS       10
#define SEQ        512
#define BATCHN     8192
#define START_TAG  8
#define STOP_TAG   9
#define NEG_INF    (-10000.0f)

// Backpointers: one u64 per (t,b), tag n's argmax in nibble 4*n. 33.5 MB scratch.
__device__ unsigned long long g_bp[(size_t)SEQ * BATCHN];

// Each thread loads the 5 feat values for ITS half of the tags.
// half=0 -> tags 0..4 (bytes 0..19), half=1 -> tags 5..9 (bytes 20..39).
// Row base = (t*BATCHN+b)*40 bytes (8-aligned), so +0,+8,+24,+32 are float2-safe.
__device__ __forceinline__ void load_half_row(float f[5],
                                               const float* __restrict__ feats,
                                               int t, int b, int half) {
    const char* base = (const char*)feats + ((size_t)t * BATCHN + (size_t)b) * (TAGS * 4);
    const float2 A = *(const float2*)(base + (half ? 24 : 0));
    const float2 B = *(const float2*)(base + (half ? 32 : 8));
    const float  s = *(const float*)(base + (half ? 20 : 16));
    f[0] = half ? s   : A.x;
    f[1] = half ? A.x : A.y;
    f[2] = half ? A.y : B.x;
    f[3] = half ? B.x : B.y;
    f[4] = half ? B.y : s;
}

__global__ __launch_bounds__(128, 1)
void crf_viterbi2(const float* __restrict__ feats,
                  const float* __restrict__ trans,
                  float* __restrict__ out) {
    const int tid   = blockIdx.x * blockDim.x + threadIdx.x;  // 16384 threads
    const int b     = tid >> 1;
    const int half  = tid & 1;          // 0: next-tags 0..4, 1: next-tags 5..9
    const int nbase = half * 5;

    // Transition rows for my 5 next-tags + STOP row (for terminal argmax).
    float T[5][TAGS];
#pragma unroll
    for (int i = 0; i < 5; i++)
#pragma unroll
        for (int p = 0; p < TAGS; p++)
            T[i][p] = __ldg(trans + (nbase + i) * TAGS + p);
    float Ts[TAGS];
#pragma unroll
    for (int p = 0; p < TAGS; p++) Ts[p] = __ldg(trans + STOP_TAG * TAGS + p);

    // init fv
    float fv[TAGS];
#pragma unroll
    for (int p = 0; p < TAGS; p++) fv[p] = NEG_INF;
    fv[START_TAG] = 0.0f;

    // software pipeline: prefetch t=0 feats
    float fpre[5];
    load_half_row(fpre, feats, 0, b, half);

    unsigned long long* __restrict__ bp_col = g_bp + b;

    for (int t = 0; t < SEQ; t++) {
        float fcur[5];
#pragma unroll
        for (int i = 0; i < 5; i++) fcur[i] = fpre[i];
        if (t + 1 < SEQ) load_half_row(fpre, feats, t + 1, b, half);

        float nf[5];
        unsigned bits = 0u;   // 5 nibbles for my tags (local order)
#pragma unroll
        for (int i = 0; i < 5; i++) {
            float v[TAGS];
#pragma unroll
            for (int p = 0; p < TAGS; p++) v[p] = fv[p] + T[i][p];
            // depth-4 FMNMX tree max (short critical path)
            float m01 = fmaxf(v[0], v[1]), m23 = fmaxf(v[2], v[3]);
            float m45 = fmaxf(v[4], v[5]), m67 = fmaxf(v[6], v[7]);
            float m89 = fmaxf(v[8], v[9]);
            float m03 = fmaxf(m01, m23),   m47 = fmaxf(m45, m67);
            float m07 = fmaxf(m03, m47);
            float m   = fmaxf(m07, m89);
            nf[i] = m + fcur[i];
            // argmax = first index equal to max (exact compare; off critical path)
            int bi = 9;
#pragma unroll
            for (int p = 8; p >= 0; --p) bi = (v[p] == m) ? p : bi;
            bits |= (unsigned)bi << (4 * i);
        }

        // exchange the other half's new fv via lane-pair shuffle
#pragma unroll
        for (int i = 0; i < 5; i++) {
            float o = __shfl_xor_sync(0xffffffffu, nf[i], 1);
            fv[i]     = half ? o     : nf[i];
            fv[i + 5] = half ? nf[i] : o;
        }

        // assemble packed backpointers on the even lane and store
        unsigned obits = __shfl_xor_sync(0xffffffffu, bits, 1);
        if (!half) {
            unsigned long long w =
                (unsigned long long)bits | ((unsigned long long)obits << 20);
            bp_col[(size_t)t * BATCHN] = w;
        }
    }

    // terminal: max/argmax over fv + trans[STOP] (both lanes compute; even stores)
    float tv[TAGS];
#pragma unroll
    for (int p = 0; p < TAGS; p++) tv[p] = fv[p] + Ts[p];
    float m01 = fmaxf(tv[0], tv[1]), m23 = fmaxf(tv[2], tv[3]);
    float m45 = fmaxf(tv[4], tv[5]), m67 = fmaxf(tv[6], tv[7]);
    float m89 = fmaxf(tv[8], tv[9]);
    float m   = fmaxf(fmaxf(fmaxf(m01, m23), fmaxf(m45, m67)), m89);
    int tag = 9;
#pragma unroll
    for (int p = 8; p >= 0; --p) tag = (tv[p] == m) ? p : tag;

    if (!half) {
        out[b] = m;
        float* __restrict__ path = out + BATCHN;
        // backtrace: loads are address-independent of tag -> prefetchable via unroll
#pragma unroll 8
        for (int t = SEQ - 1; t >= 0; t--) {
            path[(size_t)t * BATCHN + b] = (float)tag;
            unsigned long long w = bp_col[(size_t)t * BATCHN];
            tag = (int)((w >> (tag * 4)) & 0xFull);
        }
    }
}

extern "C" void kernel_launch(void* const* d_in, const int* in_sizes, int n_in,
                              void* d_out, int out_size) {
    const float* feats = (const float*)d_in[0];
    const float* trans = (const float*)d_in[1];
    float* out = (float*)d_out;

    // 16384 threads (2 per batch element), 128-thread blocks ->
    // 128 blocks, 4 warps/block -> all 4 SMSPs busy on 128 SMs.
    crf_viterbi2<<<128, 128>>>(feats, trans, out);
}

// round 3
// speedup vs baseline: 1.7827x; 1.7304x over previous
#include <cuda_runtime.h>
#include <cstdint>

#define TAGS       10
#define SEQ        512
#define BATCHN     8192
#define START_TAG  8
#define STOP_TAG   9
#define NEG_INF    (-10000.0f)

#define STAGES       8
#define BPB          64                  // batch elems per block
#define STAGE_BYTES  (BPB * TAGS * 4)    // 2560 B, contiguous in gmem
#define CHUNKS       (STAGE_BYTES / 16)  // 160 x 16B

// Backpointers: one u64 per (t,b), tag n's argmax in nibble 4*n. 33.5 MB scratch.
__device__ unsigned long long g_bp[(size_t)SEQ * BATCHN];

__device__ __forceinline__ void cp16(uint32_t s_addr, const void* g) {
    asm volatile("cp.async.ca.shared.global [%0], [%1], 16;\n"
                 :: "r"(s_addr), "l"(g));
}
__device__ __forceinline__ void cp_commit() {
    asm volatile("cp.async.commit_group;\n" ::: "memory");
}
__device__ __forceinline__ void cp_wait6() {
    asm volatile("cp.async.wait_group 6;\n" ::: "memory");
}

// tournament node: value max + first-index argmax (left wins ties, exact compares)
#define TOURN(vl, il, vr, ir, mo, io) \
    { bool _p = (vr) > (vl); mo = _p ? (vr) : (vl); io = _p ? (ir) : (il); }

__global__ __launch_bounds__(128, 1)
void crf_viterbi3(const float* __restrict__ feats,
                  const float* __restrict__ trans,
                  float* __restrict__ out) {
    __shared__ __align__(16) char stage[STAGES][STAGE_BYTES];

    const int tid  = threadIdx.x;                  // 0..127
    const int lb   = tid >> 1;                     // local batch 0..63
    const int half = tid & 1;                      // 0: tags 0..4, 1: tags 5..9
    const int b    = blockIdx.x * BPB + lb;
    const int nbase = half * 5;

    // global byte base of this block's per-step slice
    const char* gbase = (const char*)feats + (size_t)blockIdx.x * STAGE_BYTES;
    const size_t gstep = (size_t)BATCHN * TAGS * 4;   // bytes per t

    // my copy chunks (chunk tid always, chunk 128+tid if tid<32)
    const int c0 = tid;
    const bool has_c1 = (tid < 32);
    const int c1 = 128 + tid;

    uint32_t s_smem_base;
    asm("{ .reg .u64 t; cvta.to.shared.u64 t, %1; cvt.u32.u64 %0, t; }"
        : "=r"(s_smem_base) : "l"(&stage[0][0]));

    // ---- transition rows (my 5 next-tags) + STOP row ----
    float T[5][TAGS];
#pragma unroll
    for (int i = 0; i < 5; i++)
#pragma unroll
        for (int p = 0; p < TAGS; p++)
            T[i][p] = __ldg(trans + (nbase + i) * TAGS + p);
    float Ts[TAGS];
#pragma unroll
    for (int p = 0; p < TAGS; p++) Ts[p] = __ldg(trans + STOP_TAG * TAGS + p);

    float fv[TAGS];
#pragma unroll
    for (int p = 0; p < TAGS; p++) fv[p] = NEG_INF;
    fv[START_TAG] = 0.0f;

    // ---- prologue: fill stages 0..STAGES-2 with steps 0..STAGES-2 ----
#pragma unroll
    for (int s = 0; s < STAGES - 1; s++) {
        const char* g = gbase + (size_t)s * gstep;
        uint32_t sb = s_smem_base + s * STAGE_BYTES;
        cp16(sb + c0 * 16, g + c0 * 16);
        if (has_c1) cp16(sb + c1 * 16, g + c1 * 16);
        cp_commit();
    }

    // per-thread smem read offsets within a stage (overlapping f2/f1 reads)
    const int offA = lb * 40 + (half ? 24 : 0);
    const int offB = lb * 40 + (half ? 32 : 8);
    const int offS = lb * 40 + (half ? 20 : 16);

    unsigned long long* __restrict__ bp_col = g_bp + b;

    for (int t = 0; t < SEQ; t++) {
        cp_wait6();
        __syncthreads();

        // read my 5 feat values for step t from stage t%8
        const char* sp = stage[t & (STAGES - 1)];
        float2 A = *(const float2*)(sp + offA);
        float2 B = *(const float2*)(sp + offB);
        float  s = *(const float*)(sp + offS);
        float f[5];
        if (half) { f[0] = s;   f[1] = A.x; f[2] = A.y; f[3] = B.x; f[4] = B.y; }
        else      { f[0] = A.x; f[1] = A.y; f[2] = B.x; f[3] = B.y; f[4] = s;   }

        // issue prefetch for step t+STAGES-1 into stage (t-1)%8 (just freed)
        {
            int ns = t + STAGES - 1;
            if (ns < SEQ) {
                const char* g = gbase + (size_t)ns * gstep;
                uint32_t sb = s_smem_base + (ns & (STAGES - 1)) * STAGE_BYTES;
                cp16(sb + c0 * 16, g + c0 * 16);
                if (has_c1) cp16(sb + c1 * 16, g + c1 * 16);
            }
            cp_commit();
        }

        // ---- 5 next-tags: max+argmax tournament over 10 prev-tags ----
        float nf[5];
        unsigned bits = 0u;
#pragma unroll
        for (int i = 0; i < 5; i++) {
            float v0 = fv[0] + T[i][0], v1 = fv[1] + T[i][1];
            float v2 = fv[2] + T[i][2], v3 = fv[3] + T[i][3];
            float v4 = fv[4] + T[i][4], v5 = fv[5] + T[i][5];
            float v6 = fv[6] + T[i][6], v7 = fv[7] + T[i][7];
            float v8 = fv[8] + T[i][8], v9 = fv[9] + T[i][9];
            float m01, m23, m45, m67, m89, m03, m47, m07, m;
            int   i01, i23, i45, i67, i89, i03, i47, i07, bi;
            TOURN(v0, 0, v1, 1, m01, i01);
            TOURN(v2, 2, v3, 3, m23, i23);
            TOURN(v4, 4, v5, 5, m45, i45);
            TOURN(v6, 6, v7, 7, m67, i67);
            TOURN(v8, 8, v9, 9, m89, i89);
            TOURN(m01, i01, m23, i23, m03, i03);
            TOURN(m45, i45, m67, i67, m47, i47);
            TOURN(m03, i03, m47, i47, m07, i07);
            TOURN(m07, i07, m89, i89, m,   bi);
            nf[i] = m + f[i];
            bits |= (unsigned)bi << (4 * i);
        }

        // exchange halves via lane-pair shuffle
#pragma unroll
        for (int i = 0; i < 5; i++) {
            float o = __shfl_xor_sync(0xffffffffu, nf[i], 1);
            fv[i]     = half ? o     : nf[i];
            fv[i + 5] = half ? nf[i] : o;
        }
        unsigned obits = __shfl_xor_sync(0xffffffffu, bits, 1);
        if (!half) {
            unsigned long long w =
                (unsigned long long)bits | ((unsigned long long)obits << 20);
            bp_col[(size_t)t * BATCHN] = w;
        }
    }

    // ---- terminal max/argmax ----
    float tv[TAGS];
#pragma unroll
    for (int p = 0; p < TAGS; p++) tv[p] = fv[p] + Ts[p];
    float m01, m23, m45, m67, m89, m03, m47, m07, m;
    int   i01, i23, i45, i67, i89, i03, i47, i07, tag;
    TOURN(tv[0], 0, tv[1], 1, m01, i01);
    TOURN(tv[2], 2, tv[3], 3, m23, i23);
    TOURN(tv[4], 4, tv[5], 5, m45, i45);
    TOURN(tv[6], 6, tv[7], 7, m67, i67);
    TOURN(tv[8], 8, tv[9], 9, m89, i89);
    TOURN(m01, i01, m23, i23, m03, i03);
    TOURN(m45, i45, m67, i67, m47, i47);
    TOURN(m03, i03, m47, i47, m07, i07);
    TOURN(m07, i07, m89, i89, m,   tag);

    if (!half) {
        out[b] = m;
        float* __restrict__ path = out + BATCHN;
#pragma unroll 8
        for (int t = SEQ - 1; t >= 0; t--) {
            path[(size_t)t * BATCHN + b] = (float)tag;
            unsigned long long w = bp_col[(size_t)t * BATCHN];
            tag = (int)((w >> (tag * 4)) & 0xFull);
        }
    }
}

extern "C" void kernel_launch(void* const* d_in, const int* in_sizes, int n_in,
                              void* d_out, int out_size) {
    const float* feats = (const float*)d_in[0];
    const float* trans = (const float*)d_in[1];
    float* out = (float*)d_out;

    crf_viterbi3<<<BATCHN / BPB, 128>>>(feats, trans, out);   // 128 blocks
}